// round 3
// baseline (speedup 1.0000x reference)
#include <cuda_runtime.h>

// img:  [1, 3, 4096, 4096] float32
// ys,xs: [512] int32
// out:  [256, 6, 32, 32] float32 == linearized [N=512, 3, 32, 32]
//
// One CTA per (patch, channel): 512*3 = 1536 CTAs, 256 threads each.
// Each thread: 4 batched loads (MLP=4) + 4 coalesced stores.

#define H 4096
#define W 4096
#define PH 32
#define PW 32
#define NPATCH 512

__global__ __launch_bounds__(256, 8)
void patch_gather_kernel(const float* __restrict__ img,
                         const int* __restrict__ ys,
                         const int* __restrict__ xs,
                         float* __restrict__ out)
{
    const int b = blockIdx.x;          // 0..1535
    const int n = b / 3;               // patch
    const int c = b - n * 3;           // channel

    const int y0 = ys[n];
    const int x0 = xs[n];

    const float* __restrict__ img_c = img + (size_t)c * H * W;
    float* __restrict__ out_nc = out + (size_t)n * (3 * PH * PW) + (size_t)c * (PH * PW);

    // 1024 elements per CTA, 256 threads, 4 elems/thread.
    // e = tid + k*256 ; e = r*32 + j ; consecutive tid -> consecutive j.
    float v[4];
    #pragma unroll
    for (int k = 0; k < 4; k++) {
        const int e = threadIdx.x + (k << 8);
        const int j = e & 31;
        const int r = e >> 5;
        int yy = y0 + r; if (yy >= H) yy -= H;
        int xx = x0 + j; if (xx >= W) xx -= W;
        v[k] = __ldg(img_c + (size_t)yy * W + xx);
    }
    #pragma unroll
    for (int k = 0; k < 4; k++) {
        out_nc[threadIdx.x + (k << 8)] = v[k];
    }
}

extern "C" void kernel_launch(void* const* d_in, const int* in_sizes, int n_in,
                              void* d_out, int out_size)
{
    const float* img = (const float*)d_in[0];
    const int*   ys  = (const int*)d_in[1];
    const int*   xs  = (const int*)d_in[2];
    float* out = (float*)d_out;

    patch_gather_kernel<<<NPATCH * 3, 256>>>(img, ys, xs, out);
}

// round 4
// speedup vs baseline: 1.0386x; 1.0386x over previous
#include <cuda_runtime.h>

// img:  [1, 3, 4096, 4096] float32
// ys,xs: [512] int32
// out:  [256, 6, 32, 32] float32 == linearized [N=512, 3, 32, 32]
//
// One CTA per (patch, channel): 1536 CTAs x 128 threads.
// Each thread batches 8 independent LDGs (front-batched -> MLP=8/thread),
// then 8 coalesced stores. Target: maximize in-flight DRAM bytes per SM.

#define H 4096
#define W 4096
#define PH 32
#define PW 32
#define NPATCH 512

__global__ __launch_bounds__(128)
void patch_gather_kernel(const float* __restrict__ img,
                         const int* __restrict__ ys,
                         const int* __restrict__ xs,
                         float* __restrict__ out)
{
    const int b = blockIdx.x;          // 0..1535
    const int n = b / 3;               // patch
    const int c = b - n * 3;           // channel

    const int y0 = ys[n];
    const int x0 = xs[n];

    const float* __restrict__ img_c = img + (size_t)c * H * W;
    float* __restrict__ out_nc = out + (size_t)n * (3 * PH * PW) + (size_t)c * (PH * PW);

    // lane j = tid & 31 fixed across k  -> xx computed once
    const int j = threadIdx.x & 31;
    int xx = x0 + j; if (xx >= W) xx -= W;

    // 1024 elems / 128 threads = 8 rows per thread group of 32
    // e = tid + k*128 ; row r = e >> 5 = (tid>>5) + 4*k
    const int r0 = threadIdx.x >> 5;

    float v[8];
    #pragma unroll
    for (int k = 0; k < 8; k++) {
        const int r = r0 + (k << 2);
        int yy = y0 + r; if (yy >= H) yy -= H;
        v[k] = __ldg(img_c + (size_t)yy * W + xx);
    }

    #pragma unroll
    for (int k = 0; k < 8; k++) {
        out_nc[threadIdx.x + (k << 7)] = v[k];
    }
}

extern "C" void kernel_launch(void* const* d_in, const int* in_sizes, int n_in,
                              void* d_out, int out_size)
{
    const float* img = (const float*)d_in[0];
    const int*   ys  = (const int*)d_in[1];
    const int*   xs  = (const int*)d_in[2];
    float* out = (float*)d_out;

    patch_gather_kernel<<<NPATCH * 3, 128>>>(img, ys, xs, out);
}